// round 12
// baseline (speedup 1.0000x reference)
#include <cuda_runtime.h>
#include <cuda_fp16.h>
#include <cuda_bf16.h>
#include <cstdint>

#define N_NODES 100000
#define KF      192
#define OUT     128
#define NNZ     400000

#define KCHUNKS 12                 // K=192, 16 per mma
#define NT      16                 // 128 cols / 8
#define CAP     64                 // per-row edge bucket capacity

#define BUCKET_BLOCKS 196          // 196*2048 = 401408 >= NNZ
#define EDGES_PER_BUCKET_BLOCK 2048
#define TILE_BLOCKS ((N_NODES + 127) / 128)     // 782
#define FUSED_BLOCKS (BUCKET_BLOCKS + TILE_BLOCKS)

// ---------------------------------------------------------------------------
// Global scratch
// g_cnt[0..N_NODES-1] : per-row counts,  g_cnt[N_NODES] : overflow count
// ---------------------------------------------------------------------------
__device__ float  g_Y[(size_t)N_NODES * OUT];
__device__ float4 g_tfrag[KCHUNKS * NT * 32];       // fp16 hi/lo B-fragments
__device__ int    g_cnt[N_NODES + 1];
__device__ __align__(16) uint2 g_bkt[(size_t)N_NODES * CAP];  // {col, val bits}
__device__ int    g_ovf_row[NNZ];                   // overflow rows
__device__ uint2  g_ovf_cv[NNZ];                    // overflow {col, val bits}

// ---------------------------------------------------------------------------
// fp16 helpers
// ---------------------------------------------------------------------------
__device__ __forceinline__ uint32_t pack_h2(float a, float b) {
    __half2 h = __floats2half2_rn(a, b);
    return *(uint32_t*)&h;
}
__device__ __forceinline__ float2 unpack_h2(uint32_t u) {
    __half2 h = *(__half2*)&u;
    return __half22float2(h);
}
__device__ __forceinline__ void mma_f16(float* c, const uint32_t* a,
                                        uint32_t b0, uint32_t b1) {
    asm volatile(
        "mma.sync.aligned.m16n8k16.row.col.f32.f16.f16.f32 "
        "{%0,%1,%2,%3}, {%4,%5,%6,%7}, {%8,%9}, {%0,%1,%2,%3};"
        : "+f"(c[0]), "+f"(c[1]), "+f"(c[2]), "+f"(c[3])
        : "r"(a[0]), "r"(a[1]), "r"(a[2]), "r"(a[3]), "r"(b0), "r"(b1));
}

// ---------------------------------------------------------------------------
// Frag prep: build theta fp16 hi/lo B-fragments (24 blocks).
// Counter zeroing is done by cudaMemsetAsync in kernel_launch.
// ---------------------------------------------------------------------------
__global__ __launch_bounds__(256)
void frag_kernel(const float* __restrict__ theta) {
    int i = blockIdx.x * 256 + threadIdx.x;
    if (i >= KCHUNKS * NT * 32) return;
    int lane = i & 31;
    int tt   = (i >> 5) & 15;
    int c    = i >> 9;
    int g    = lane >> 2;
    int tig  = lane & 3;
    int k    = c * 16 + 2 * tig;
    int n    = tt * 8 + g;

    float f00 = theta[(k    ) * OUT + n];
    float f01 = theta[(k + 1) * OUT + n];
    float f10 = theta[(k + 8) * OUT + n];
    float f11 = theta[(k + 9) * OUT + n];

    uint32_t bh0 = pack_h2(f00, f01);
    uint32_t bh1 = pack_h2(f10, f11);
    float2 h0 = unpack_h2(bh0), h1 = unpack_h2(bh1);
    uint32_t bl0 = pack_h2(f00 - h0.x, f01 - h0.y);
    uint32_t bl1 = pack_h2(f10 - h1.x, f11 - h1.y);

    g_tfrag[i] = make_float4(__uint_as_float(bh0), __uint_as_float(bh1),
                             __uint_as_float(bl0), __uint_as_float(bl1));
}

// ---------------------------------------------------------------------------
// Fused launch, role-split blocks:
//   blockIdx.x <  BUCKET_BLOCKS : bucket a 2048-edge slice (scheduled first,
//                                 overlaps with tile blocks' MMA work)
//   blockIdx.x >= BUCKET_BLOCKS : one 128x128 GEMM tile
// ---------------------------------------------------------------------------
#define A_STRIDE_B 400                    // 200 halves per row (192 + 8 pad)
#define SM_ALO     (128 * A_STRIDE_B)
#define GEMM_SMEM  (2 * 128 * A_STRIDE_B) // 102,400 B

__global__ __launch_bounds__(256, 2)
void gemm_bucket_kernel(const float* __restrict__ x,
                        const int* __restrict__ row_idx,
                        const int* __restrict__ col_idx,
                        const float* __restrict__ vals,
                        float* __restrict__ Y) {
    extern __shared__ char smem[];
    const int tid = threadIdx.x;

    // ---------------- bucket role ----------------
    if (blockIdx.x < BUCKET_BLOCKS) {
        int base = blockIdx.x * EDGES_PER_BUCKET_BLOCK + tid;
#pragma unroll
        for (int j = 0; j < 8; j++) {
            int e = base + j * 256;
            if (e < NNZ) {
                int   r = __ldg(row_idx + e);
                int   c = __ldg(col_idx + e);
                float v = __ldg(vals + e);
                int pos = atomicAdd(&g_cnt[r], 1);
                if (pos < CAP) {
                    g_bkt[(size_t)r * CAP + pos] =
                        make_uint2((unsigned)c, __float_as_uint(v));
                } else {
                    int o = atomicAdd(&g_cnt[N_NODES], 1);
                    g_ovf_row[o] = r;
                    g_ovf_cv[o]  = make_uint2((unsigned)c, __float_as_uint(v));
                }
            }
        }
        return;
    }

    // ---------------- GEMM tile role ----------------
    char* sAh = smem;
    char* sAl = smem + SM_ALO;
    const int block_row = (blockIdx.x - BUCKET_BLOCKS) * 128;

    for (int i = tid; i < 128 * 48; i += 256) {
        int r = i / 48;
        int q = i - r * 48;
        int row = block_row + r;
        float4 v = make_float4(0.f, 0.f, 0.f, 0.f);
        if (row < N_NODES) v = ((const float4*)(x + (size_t)row * KF))[q];

        uint32_t h01 = pack_h2(v.x, v.y);
        uint32_t h23 = pack_h2(v.z, v.w);
        float2 f01 = unpack_h2(h01), f23 = unpack_h2(h23);
        uint32_t l01 = pack_h2(v.x - f01.x, v.y - f01.y);
        uint32_t l23 = pack_h2(v.z - f23.x, v.w - f23.y);

        uint32_t off = r * A_STRIDE_B + q * 8;
        *(uint2*)(sAh + off) = make_uint2(h01, h23);
        *(uint2*)(sAl + off) = make_uint2(l01, l23);
    }
    __syncthreads();

    const int lane     = tid & 31;
    const int wid      = tid >> 5;
    const int warp_row = wid & 3;
    const int warp_col = wid >> 2;
    const int g        = lane >> 2;
    const int tig      = lane & 3;

    float acc[2][8][4];
#pragma unroll
    for (int m = 0; m < 2; m++)
#pragma unroll
        for (int t = 0; t < 8; t++)
#pragma unroll
            for (int j = 0; j < 4; j++) acc[m][t][j] = 0.0f;

    const uint32_t abase = (warp_row * 32 + g) * A_STRIDE_B + 2 * tig * 2;
    const float4*  tf    = g_tfrag + (size_t)(warp_col * 8) * 32 + lane;

#pragma unroll 2
    for (int c = 0; c < KCHUNKS; c++) {
        const uint32_t koff = c * 32;
        uint32_t ah[2][4], al[2][4];
#pragma unroll
        for (int m = 0; m < 2; m++) {
            uint32_t o = abase + m * 16 * A_STRIDE_B + koff;
            ah[m][0] = *(const uint32_t*)(sAh + o);
            ah[m][1] = *(const uint32_t*)(sAh + o + 8 * A_STRIDE_B);
            ah[m][2] = *(const uint32_t*)(sAh + o + 16);
            ah[m][3] = *(const uint32_t*)(sAh + o + 8 * A_STRIDE_B + 16);
            al[m][0] = *(const uint32_t*)(sAl + o);
            al[m][1] = *(const uint32_t*)(sAl + o + 8 * A_STRIDE_B);
            al[m][2] = *(const uint32_t*)(sAl + o + 16);
            al[m][3] = *(const uint32_t*)(sAl + o + 8 * A_STRIDE_B + 16);
        }
#pragma unroll
        for (int t = 0; t < 8; t++) {
            float4 bf = __ldg(tf + ((size_t)c * NT + t) * 32);
            uint32_t bh0 = __float_as_uint(bf.x), bh1 = __float_as_uint(bf.y);
            uint32_t bl0 = __float_as_uint(bf.z), bl1 = __float_as_uint(bf.w);
#pragma unroll
            for (int m = 0; m < 2; m++) {
                mma_f16(acc[m][t], ah[m], bh0, bh1);
                mma_f16(acc[m][t], al[m], bh0, bh1);
                mma_f16(acc[m][t], ah[m], bl0, bl1);
            }
        }
    }

#pragma unroll
    for (int m = 0; m < 2; m++) {
        int r0 = block_row + warp_row * 32 + m * 16 + g;
        int r1 = r0 + 8;
#pragma unroll
        for (int t = 0; t < 8; t++) {
            int col = warp_col * 64 + t * 8 + 2 * tig;
            if (r0 < N_NODES)
                *(float2*)(Y + (size_t)r0 * OUT + col) = make_float2(acc[m][t][0], acc[m][t][1]);
            if (r1 < N_NODES)
                *(float2*)(Y + (size_t)r1 * OUT + col) = make_float2(acc[m][t][2], acc[m][t][3]);
        }
    }
}

// ---------------------------------------------------------------------------
// Gather SpMM: TWO warps per row (half-row of 64 floats each, float2/lane).
// Doubles chip-wide load parallelism vs one-warp-per-row; batch-4 MLP per
// warp. Overflowed rows (cnt > CAP, normally none) scan the overflow list
// in-warp before the single non-atomic store.
// ---------------------------------------------------------------------------
__global__ __launch_bounds__(256)
void spmm_gather_kernel(const float* __restrict__ Y, float* __restrict__ out) {
    int gw   = blockIdx.x * 8 + (threadIdx.x >> 5);   // global warp id
    int row  = gw >> 1;
    int half = gw & 1;
    int lane = threadIdx.x & 31;
    if (row >= N_NODES) return;

    int cnt_full = g_cnt[row];
    int cnt = cnt_full > CAP ? CAP : cnt_full;

    const uint2* bkt = g_bkt + (size_t)row * CAP;
    const int foff = half * 64 + lane * 2;            // float offset in row
    float2 acc = make_float2(0.f, 0.f);

    int nb = cnt >> 2;
    for (int b = 0; b < nb; b++) {
        uint4 e01 = *(const uint4*)(bkt + 4 * b);
        uint4 e23 = *(const uint4*)(bkt + 4 * b + 2);
        float2 y0 = __ldg((const float2*)(Y + (size_t)e01.x * OUT + foff));
        float2 y1 = __ldg((const float2*)(Y + (size_t)e01.z * OUT + foff));
        float2 y2 = __ldg((const float2*)(Y + (size_t)e23.x * OUT + foff));
        float2 y3 = __ldg((const float2*)(Y + (size_t)e23.z * OUT + foff));
        float v0 = __uint_as_float(e01.y), v1 = __uint_as_float(e01.w);
        float v2 = __uint_as_float(e23.y), v3 = __uint_as_float(e23.w);
        acc.x += v0 * y0.x; acc.y += v0 * y0.y;
        acc.x += v1 * y1.x; acc.y += v1 * y1.y;
        acc.x += v2 * y2.x; acc.y += v2 * y2.y;
        acc.x += v3 * y3.x; acc.y += v3 * y3.y;
    }
    for (int i = nb * 4; i < cnt; i++) {
        uint2 e = bkt[i];
        float2 y = __ldg((const float2*)(Y + (size_t)e.x * OUT + foff));
        float v = __uint_as_float(e.y);
        acc.x += v * y.x; acc.y += v * y.y;
    }

    // Overflow: only owning warps scan (normally cnt_full <= CAP: skipped).
    if (cnt_full > CAP) {
        int n = g_cnt[N_NODES];
        for (int i = 0; i < n; i++) {
            if (g_ovf_row[i] == row) {
                uint2 e = g_ovf_cv[i];
                float2 y = __ldg((const float2*)(Y + (size_t)e.x * OUT + foff));
                float v = __uint_as_float(e.y);
                acc.x += v * y.x; acc.y += v * y.y;
            }
        }
    }

    *(float2*)(out + (size_t)row * OUT + foff) = acc;
}

// ---------------------------------------------------------------------------
extern "C" void kernel_launch(void* const* d_in, const int* in_sizes, int n_in,
                              void* d_out, int out_size) {
    const int*   row_idx = (const int*)d_in[0];
    const int*   col_idx = (const int*)d_in[1];
    const float* vals    = (const float*)d_in[2];
    const float* x       = (const float*)d_in[3];
    const float* theta   = (const float*)d_in[4];
    float*       out     = (float*)d_out;

    float* Y;
    cudaGetSymbolAddress((void**)&Y, g_Y);
    int* cnt;
    cudaGetSymbolAddress((void**)&cnt, g_cnt);

    // Zero per-row counters + overflow count (full-bandwidth memset).
    cudaMemsetAsync(cnt, 0, (N_NODES + 1) * sizeof(int), 0);

    // Theta fp16 hi/lo fragments (24 blocks).
    frag_kernel<<<(KCHUNKS * NT * 32 + 255) / 256, 256>>>(theta);

    // Fused: bucket blocks (first) + GEMM tile blocks, overlapping.
    cudaFuncSetAttribute(gemm_bucket_kernel,
                         cudaFuncAttributeMaxDynamicSharedMemorySize, GEMM_SMEM);
    gemm_bucket_kernel<<<FUSED_BLOCKS, 256, GEMM_SMEM>>>(x, row_idx, col_idx, vals, Y);

    // Gather: 2 warps per row (handles overflow in-warp; no extra kernel).
    spmm_gather_kernel<<<(2 * N_NODES + 7) / 8, 256>>>(Y, out);
}

// round 13
// speedup vs baseline: 1.0995x; 1.0995x over previous
#include <cuda_runtime.h>
#include <cuda_fp16.h>
#include <cuda_bf16.h>
#include <cstdint>

#define N_NODES 100000
#define KF      192
#define OUT     128
#define NNZ     400000

#define KCHUNKS 12                 // K=192, 16 per mma
#define NT      16                 // 128 cols / 8
#define CAP     64                 // per-row edge bucket capacity

#define BUCKET_BLOCKS 196          // 196*2048 = 401408 >= NNZ
#define EDGES_PER_BUCKET_BLOCK 2048
#define TILE_BLOCKS ((N_NODES + 127) / 128)     // 782
#define FUSED_BLOCKS (BUCKET_BLOCKS + TILE_BLOCKS)

// ---------------------------------------------------------------------------
// Global scratch
// g_cnt[0..N_NODES-1] : per-row counts,  g_cnt[N_NODES] : overflow count
// ---------------------------------------------------------------------------
__device__ float  g_Y[(size_t)N_NODES * OUT];
__device__ float4 g_tfrag[KCHUNKS * NT * 32];       // fp16 hi/lo B-fragments
__device__ int    g_cnt[N_NODES + 1];
__device__ __align__(16) uint2 g_bkt[(size_t)N_NODES * CAP];  // {col, val bits}
__device__ int    g_ovf_row[NNZ];                   // overflow rows
__device__ uint2  g_ovf_cv[NNZ];                    // overflow {col, val bits}

// ---------------------------------------------------------------------------
// fp16 helpers
// ---------------------------------------------------------------------------
__device__ __forceinline__ uint32_t pack_h2(float a, float b) {
    __half2 h = __floats2half2_rn(a, b);
    return *(uint32_t*)&h;
}
__device__ __forceinline__ float2 unpack_h2(uint32_t u) {
    __half2 h = *(__half2*)&u;
    return __half22float2(h);
}
__device__ __forceinline__ void mma_f16(float* c, const uint32_t* a,
                                        uint32_t b0, uint32_t b1) {
    asm volatile(
        "mma.sync.aligned.m16n8k16.row.col.f32.f16.f16.f32 "
        "{%0,%1,%2,%3}, {%4,%5,%6,%7}, {%8,%9}, {%0,%1,%2,%3};"
        : "+f"(c[0]), "+f"(c[1]), "+f"(c[2]), "+f"(c[3])
        : "r"(a[0]), "r"(a[1]), "r"(a[2]), "r"(a[3]), "r"(b0), "r"(b1));
}

// ---------------------------------------------------------------------------
// Prep: zero counters + build theta fp16 hi/lo B-fragments. One launch.
// ---------------------------------------------------------------------------
__global__ __launch_bounds__(256)
void prep_kernel(const float* __restrict__ theta) {
    int i = blockIdx.x * 256 + threadIdx.x;
    if (i <= N_NODES) g_cnt[i] = 0;

    if (i < KCHUNKS * NT * 32) {
        int lane = i & 31;
        int tt   = (i >> 5) & 15;
        int c    = i >> 9;
        int g    = lane >> 2;
        int tig  = lane & 3;
        int k    = c * 16 + 2 * tig;
        int n    = tt * 8 + g;

        float f00 = theta[(k    ) * OUT + n];
        float f01 = theta[(k + 1) * OUT + n];
        float f10 = theta[(k + 8) * OUT + n];
        float f11 = theta[(k + 9) * OUT + n];

        uint32_t bh0 = pack_h2(f00, f01);
        uint32_t bh1 = pack_h2(f10, f11);
        float2 h0 = unpack_h2(bh0), h1 = unpack_h2(bh1);
        uint32_t bl0 = pack_h2(f00 - h0.x, f01 - h0.y);
        uint32_t bl1 = pack_h2(f10 - h1.x, f11 - h1.y);

        g_tfrag[i] = make_float4(__uint_as_float(bh0), __uint_as_float(bh1),
                                 __uint_as_float(bl0), __uint_as_float(bl1));
    }
}

// ---------------------------------------------------------------------------
// Fused launch, role-split blocks:
//   blockIdx.x <  BUCKET_BLOCKS : bucket a 2048-edge slice (scheduled first,
//                                 overlaps with tile blocks' MMA work)
//   blockIdx.x >= BUCKET_BLOCKS : one 128x128 GEMM tile
// ---------------------------------------------------------------------------
#define A_STRIDE_B 400                    // 200 halves per row (192 + 8 pad)
#define SM_ALO     (128 * A_STRIDE_B)
#define GEMM_SMEM  (2 * 128 * A_STRIDE_B) // 102,400 B

__global__ __launch_bounds__(256, 2)
void gemm_bucket_kernel(const float* __restrict__ x,
                        const int* __restrict__ row_idx,
                        const int* __restrict__ col_idx,
                        const float* __restrict__ vals,
                        float* __restrict__ Y) {
    extern __shared__ char smem[];
    const int tid = threadIdx.x;

    // ---------------- bucket role ----------------
    if (blockIdx.x < BUCKET_BLOCKS) {
        int base = blockIdx.x * EDGES_PER_BUCKET_BLOCK + tid;
#pragma unroll
        for (int j = 0; j < 8; j++) {
            int e = base + j * 256;
            if (e < NNZ) {
                int   r = __ldg(row_idx + e);
                int   c = __ldg(col_idx + e);
                float v = __ldg(vals + e);
                int pos = atomicAdd(&g_cnt[r], 1);
                if (pos < CAP) {
                    g_bkt[(size_t)r * CAP + pos] =
                        make_uint2((unsigned)c, __float_as_uint(v));
                } else {
                    int o = atomicAdd(&g_cnt[N_NODES], 1);
                    g_ovf_row[o] = r;
                    g_ovf_cv[o]  = make_uint2((unsigned)c, __float_as_uint(v));
                }
            }
        }
        return;
    }

    // ---------------- GEMM tile role ----------------
    char* sAh = smem;
    char* sAl = smem + SM_ALO;
    const int block_row = (blockIdx.x - BUCKET_BLOCKS) * 128;

    for (int i = tid; i < 128 * 48; i += 256) {
        int r = i / 48;
        int q = i - r * 48;
        int row = block_row + r;
        float4 v = make_float4(0.f, 0.f, 0.f, 0.f);
        if (row < N_NODES) v = ((const float4*)(x + (size_t)row * KF))[q];

        uint32_t h01 = pack_h2(v.x, v.y);
        uint32_t h23 = pack_h2(v.z, v.w);
        float2 f01 = unpack_h2(h01), f23 = unpack_h2(h23);
        uint32_t l01 = pack_h2(v.x - f01.x, v.y - f01.y);
        uint32_t l23 = pack_h2(v.z - f23.x, v.w - f23.y);

        uint32_t off = r * A_STRIDE_B + q * 8;
        *(uint2*)(sAh + off) = make_uint2(h01, h23);
        *(uint2*)(sAl + off) = make_uint2(l01, l23);
    }
    __syncthreads();

    const int lane     = tid & 31;
    const int wid      = tid >> 5;
    const int warp_row = wid & 3;
    const int warp_col = wid >> 2;
    const int g        = lane >> 2;
    const int tig      = lane & 3;

    float acc[2][8][4];
#pragma unroll
    for (int m = 0; m < 2; m++)
#pragma unroll
        for (int t = 0; t < 8; t++)
#pragma unroll
            for (int j = 0; j < 4; j++) acc[m][t][j] = 0.0f;

    const uint32_t abase = (warp_row * 32 + g) * A_STRIDE_B + 2 * tig * 2;
    const float4*  tf    = g_tfrag + (size_t)(warp_col * 8) * 32 + lane;

#pragma unroll 2
    for (int c = 0; c < KCHUNKS; c++) {
        const uint32_t koff = c * 32;
        uint32_t ah[2][4], al[2][4];
#pragma unroll
        for (int m = 0; m < 2; m++) {
            uint32_t o = abase + m * 16 * A_STRIDE_B + koff;
            ah[m][0] = *(const uint32_t*)(sAh + o);
            ah[m][1] = *(const uint32_t*)(sAh + o + 8 * A_STRIDE_B);
            ah[m][2] = *(const uint32_t*)(sAh + o + 16);
            ah[m][3] = *(const uint32_t*)(sAh + o + 8 * A_STRIDE_B + 16);
            al[m][0] = *(const uint32_t*)(sAl + o);
            al[m][1] = *(const uint32_t*)(sAl + o + 8 * A_STRIDE_B);
            al[m][2] = *(const uint32_t*)(sAl + o + 16);
            al[m][3] = *(const uint32_t*)(sAl + o + 8 * A_STRIDE_B + 16);
        }
#pragma unroll
        for (int t = 0; t < 8; t++) {
            float4 bf = __ldg(tf + ((size_t)c * NT + t) * 32);
            uint32_t bh0 = __float_as_uint(bf.x), bh1 = __float_as_uint(bf.y);
            uint32_t bl0 = __float_as_uint(bf.z), bl1 = __float_as_uint(bf.w);
#pragma unroll
            for (int m = 0; m < 2; m++) {
                mma_f16(acc[m][t], ah[m], bh0, bh1);
                mma_f16(acc[m][t], al[m], bh0, bh1);
                mma_f16(acc[m][t], ah[m], bl0, bl1);
            }
        }
    }

#pragma unroll
    for (int m = 0; m < 2; m++) {
        int r0 = block_row + warp_row * 32 + m * 16 + g;
        int r1 = r0 + 8;
#pragma unroll
        for (int t = 0; t < 8; t++) {
            int col = warp_col * 64 + t * 8 + 2 * tig;
            if (r0 < N_NODES)
                *(float2*)(Y + (size_t)r0 * OUT + col) = make_float2(acc[m][t][0], acc[m][t][1]);
            if (r1 < N_NODES)
                *(float2*)(Y + (size_t)r1 * OUT + col) = make_float2(acc[m][t][2], acc[m][t][3]);
        }
    }
}

// ---------------------------------------------------------------------------
// Gather SpMM: ONE warp per row (float4/lane, LDG.128), batch-4 MLP with
// unroll-2 so ptxas can front-batch up to 8 independent Y loads. 512-thread
// blocks to halve wave-transition overhead. Overflowed rows (cnt > CAP,
// normally none) scan the overflow list in-warp before the single store.
// ---------------------------------------------------------------------------
__global__ __launch_bounds__(512)
void spmm_gather_kernel(const float* __restrict__ Y, float* __restrict__ out) {
    int row  = blockIdx.x * 16 + (threadIdx.x >> 5);
    int lane = threadIdx.x & 31;
    if (row >= N_NODES) return;

    int cnt_full = g_cnt[row];
    int cnt = cnt_full > CAP ? CAP : cnt_full;

    const uint2* bkt = g_bkt + (size_t)row * CAP;
    float4 acc = make_float4(0.f, 0.f, 0.f, 0.f);

    int nb = cnt >> 2;
#pragma unroll 2
    for (int b = 0; b < nb; b++) {
        uint4 e01 = *(const uint4*)(bkt + 4 * b);
        uint4 e23 = *(const uint4*)(bkt + 4 * b + 2);
        float4 y0 = __ldg((const float4*)(Y + (size_t)e01.x * OUT) + lane);
        float4 y1 = __ldg((const float4*)(Y + (size_t)e01.z * OUT) + lane);
        float4 y2 = __ldg((const float4*)(Y + (size_t)e23.x * OUT) + lane);
        float4 y3 = __ldg((const float4*)(Y + (size_t)e23.z * OUT) + lane);
        float v0 = __uint_as_float(e01.y), v1 = __uint_as_float(e01.w);
        float v2 = __uint_as_float(e23.y), v3 = __uint_as_float(e23.w);
        acc.x += v0 * y0.x; acc.y += v0 * y0.y; acc.z += v0 * y0.z; acc.w += v0 * y0.w;
        acc.x += v1 * y1.x; acc.y += v1 * y1.y; acc.z += v1 * y1.z; acc.w += v1 * y1.w;
        acc.x += v2 * y2.x; acc.y += v2 * y2.y; acc.z += v2 * y2.z; acc.w += v2 * y2.w;
        acc.x += v3 * y3.x; acc.y += v3 * y3.y; acc.z += v3 * y3.z; acc.w += v3 * y3.w;
    }
    for (int i = nb * 4; i < cnt; i++) {
        uint2 e = bkt[i];
        float4 y = __ldg((const float4*)(Y + (size_t)e.x * OUT) + lane);
        float v = __uint_as_float(e.y);
        acc.x += v * y.x; acc.y += v * y.y; acc.z += v * y.z; acc.w += v * y.w;
    }

    // Overflow: only the owning warp scans (normally cnt_full <= CAP: skipped).
    if (cnt_full > CAP) {
        int n = g_cnt[N_NODES];
        for (int i = 0; i < n; i++) {
            if (g_ovf_row[i] == row) {
                uint2 e = g_ovf_cv[i];
                float4 y = __ldg((const float4*)(Y + (size_t)e.x * OUT) + lane);
                float v = __uint_as_float(e.y);
                acc.x += v * y.x; acc.y += v * y.y; acc.z += v * y.z; acc.w += v * y.w;
            }
        }
    }

    ((float4*)(out + (size_t)row * OUT))[lane] = acc;
}

// ---------------------------------------------------------------------------
extern "C" void kernel_launch(void* const* d_in, const int* in_sizes, int n_in,
                              void* d_out, int out_size) {
    const int*   row_idx = (const int*)d_in[0];
    const int*   col_idx = (const int*)d_in[1];
    const float* vals    = (const float*)d_in[2];
    const float* x       = (const float*)d_in[3];
    const float* theta   = (const float*)d_in[4];
    float*       out     = (float*)d_out;

    float* Y;
    cudaGetSymbolAddress((void**)&Y, g_Y);

    // Prep: zero counters + theta frags (one launch).
    prep_kernel<<<(N_NODES + 256) / 256, 256>>>(theta);

    // Fused: bucket blocks (first) + GEMM tile blocks, overlapping.
    cudaFuncSetAttribute(gemm_bucket_kernel,
                         cudaFuncAttributeMaxDynamicSharedMemorySize, GEMM_SMEM);
    gemm_bucket_kernel<<<FUSED_BLOCKS, 256, GEMM_SMEM>>>(x, row_idx, col_idx, vals, Y);

    // Gather: 1 warp per row, 512-thread blocks.
    spmm_gather_kernel<<<(N_NODES + 15) / 16, 512>>>(Y, out);
}

// round 14
// speedup vs baseline: 1.1454x; 1.0418x over previous
#include <cuda_runtime.h>
#include <cuda_fp16.h>
#include <cuda_bf16.h>
#include <cstdint>

#define N_NODES 100000
#define KF      192
#define OUT     128
#define NNZ     400000

#define KCHUNKS 12                 // K=192, 16 per mma
#define NT      16                 // 128 cols / 8
#define CAP     64                 // per-row edge bucket capacity

#define FRAG_BLOCKS   24           // 24*256 = 6144 frag entries
#define BUCKET_BLOCKS 196          // 196*2048 = 401408 >= NNZ
#define EDGES_PER_BUCKET_BLOCK 2048
#define TILE_BLOCKS ((N_NODES + 127) / 128)     // 782
#define FUSED_BLOCKS (FRAG_BLOCKS + BUCKET_BLOCKS + TILE_BLOCKS)

// ---------------------------------------------------------------------------
// Global scratch. All state is self-cleaning across calls:
//  - g_cnt[row] zeroed by the gather warp that owns the row
//  - g_cnt[N_NODES] (overflow count) + g_frag_done zeroed by row-0's warp
//  First call relies on static zero-init of __device__ globals.
// ---------------------------------------------------------------------------
__device__ float  g_Y[(size_t)N_NODES * OUT];
__device__ float4 g_tfrag[KCHUNKS * NT * 32];       // fp16 hi/lo B-fragments
__device__ int    g_cnt[N_NODES + 1];
__device__ int    g_frag_done;                      // frag-role completion flag
__device__ __align__(16) uint2 g_bkt[(size_t)N_NODES * CAP];  // {col, val bits}
__device__ int    g_ovf_row[NNZ];                   // overflow rows
__device__ uint2  g_ovf_cv[NNZ];                    // overflow {col, val bits}

// ---------------------------------------------------------------------------
// fp16 helpers
// ---------------------------------------------------------------------------
__device__ __forceinline__ uint32_t pack_h2(float a, float b) {
    __half2 h = __floats2half2_rn(a, b);
    return *(uint32_t*)&h;
}
__device__ __forceinline__ float2 unpack_h2(uint32_t u) {
    __half2 h = *(__half2*)&u;
    return __half22float2(h);
}
__device__ __forceinline__ void mma_f16(float* c, const uint32_t* a,
                                        uint32_t b0, uint32_t b1) {
    asm volatile(
        "mma.sync.aligned.m16n8k16.row.col.f32.f16.f16.f32 "
        "{%0,%1,%2,%3}, {%4,%5,%6,%7}, {%8,%9}, {%0,%1,%2,%3};"
        : "+f"(c[0]), "+f"(c[1]), "+f"(c[2]), "+f"(c[3])
        : "r"(a[0]), "r"(a[1]), "r"(a[2]), "r"(a[3]), "r"(b0), "r"(b1));
}

// ---------------------------------------------------------------------------
// Fused launch, 3 block roles (in scheduling order):
//   [0, FRAG_BLOCKS)              : build theta fp16 hi/lo B-fragments, then
//                                   fence + bump g_frag_done
//   [FRAG_BLOCKS, +BUCKET_BLOCKS) : bucket a 2048-edge slice
//   rest                          : one 128x128 GEMM tile; stages A, then
//                                   spins on g_frag_done before the mainloop
// ---------------------------------------------------------------------------
#define A_STRIDE_B 400                    // 200 halves per row (192 + 8 pad)
#define SM_ALO     (128 * A_STRIDE_B)
#define GEMM_SMEM  (2 * 128 * A_STRIDE_B) // 102,400 B

__global__ __launch_bounds__(256, 2)
void gemm_fused_kernel(const float* __restrict__ x,
                       const int* __restrict__ row_idx,
                       const int* __restrict__ col_idx,
                       const float* __restrict__ vals,
                       const float* __restrict__ theta,
                       float* __restrict__ Y) {
    extern __shared__ char smem[];
    const int tid = threadIdx.x;

    // ---------------- frag role ----------------
    if (blockIdx.x < FRAG_BLOCKS) {
        int i = blockIdx.x * 256 + tid;   // i < 6144 always
        int lane = i & 31;
        int tt   = (i >> 5) & 15;
        int c    = i >> 9;
        int g    = lane >> 2;
        int tig  = lane & 3;
        int k    = c * 16 + 2 * tig;
        int n    = tt * 8 + g;

        float f00 = theta[(k    ) * OUT + n];
        float f01 = theta[(k + 1) * OUT + n];
        float f10 = theta[(k + 8) * OUT + n];
        float f11 = theta[(k + 9) * OUT + n];

        uint32_t bh0 = pack_h2(f00, f01);
        uint32_t bh1 = pack_h2(f10, f11);
        float2 h0 = unpack_h2(bh0), h1 = unpack_h2(bh1);
        uint32_t bl0 = pack_h2(f00 - h0.x, f01 - h0.y);
        uint32_t bl1 = pack_h2(f10 - h1.x, f11 - h1.y);

        g_tfrag[i] = make_float4(__uint_as_float(bh0), __uint_as_float(bh1),
                                 __uint_as_float(bl0), __uint_as_float(bl1));
        __threadfence();
        __syncthreads();
        if (tid == 0) atomicAdd(&g_frag_done, 1);
        return;
    }

    // ---------------- bucket role ----------------
    if (blockIdx.x < FRAG_BLOCKS + BUCKET_BLOCKS) {
        int base = (blockIdx.x - FRAG_BLOCKS) * EDGES_PER_BUCKET_BLOCK + tid;
#pragma unroll
        for (int j = 0; j < 8; j++) {
            int e = base + j * 256;
            if (e < NNZ) {
                int   r = __ldg(row_idx + e);
                int   c = __ldg(col_idx + e);
                float v = __ldg(vals + e);
                int pos = atomicAdd(&g_cnt[r], 1);
                if (pos < CAP) {
                    g_bkt[(size_t)r * CAP + pos] =
                        make_uint2((unsigned)c, __float_as_uint(v));
                } else {
                    int o = atomicAdd(&g_cnt[N_NODES], 1);
                    g_ovf_row[o] = r;
                    g_ovf_cv[o]  = make_uint2((unsigned)c, __float_as_uint(v));
                }
            }
        }
        return;
    }

    // ---------------- GEMM tile role ----------------
    char* sAh = smem;
    char* sAl = smem + SM_ALO;
    const int block_row = (blockIdx.x - FRAG_BLOCKS - BUCKET_BLOCKS) * 128;

    for (int i = tid; i < 128 * 48; i += 256) {
        int r = i / 48;
        int q = i - r * 48;
        int row = block_row + r;
        float4 v = make_float4(0.f, 0.f, 0.f, 0.f);
        if (row < N_NODES) v = ((const float4*)(x + (size_t)row * KF))[q];

        uint32_t h01 = pack_h2(v.x, v.y);
        uint32_t h23 = pack_h2(v.z, v.w);
        float2 f01 = unpack_h2(h01), f23 = unpack_h2(h23);
        uint32_t l01 = pack_h2(v.x - f01.x, v.y - f01.y);
        uint32_t l23 = pack_h2(v.z - f23.x, v.w - f23.y);

        uint32_t off = r * A_STRIDE_B + q * 8;
        *(uint2*)(sAh + off) = make_uint2(h01, h23);
        *(uint2*)(sAl + off) = make_uint2(l01, l23);
    }
    __syncthreads();

    // Wait for frag role (normally already done: frag blocks are wave-1).
    if (tid == 0) {
        while (*(volatile int*)&g_frag_done < FRAG_BLOCKS) { }
    }
    __syncthreads();

    const int lane     = tid & 31;
    const int wid      = tid >> 5;
    const int warp_row = wid & 3;
    const int warp_col = wid >> 2;
    const int g        = lane >> 2;
    const int tig      = lane & 3;

    float acc[2][8][4];
#pragma unroll
    for (int m = 0; m < 2; m++)
#pragma unroll
        for (int t = 0; t < 8; t++)
#pragma unroll
            for (int j = 0; j < 4; j++) acc[m][t][j] = 0.0f;

    const uint32_t abase = (warp_row * 32 + g) * A_STRIDE_B + 2 * tig * 2;
    const float4*  tf    = g_tfrag + (size_t)(warp_col * 8) * 32 + lane;

#pragma unroll 2
    for (int c = 0; c < KCHUNKS; c++) {
        const uint32_t koff = c * 32;
        uint32_t ah[2][4], al[2][4];
#pragma unroll
        for (int m = 0; m < 2; m++) {
            uint32_t o = abase + m * 16 * A_STRIDE_B + koff;
            ah[m][0] = *(const uint32_t*)(sAh + o);
            ah[m][1] = *(const uint32_t*)(sAh + o + 8 * A_STRIDE_B);
            ah[m][2] = *(const uint32_t*)(sAh + o + 16);
            ah[m][3] = *(const uint32_t*)(sAh + o + 8 * A_STRIDE_B + 16);
            al[m][0] = *(const uint32_t*)(sAl + o);
            al[m][1] = *(const uint32_t*)(sAl + o + 8 * A_STRIDE_B);
            al[m][2] = *(const uint32_t*)(sAl + o + 16);
            al[m][3] = *(const uint32_t*)(sAl + o + 8 * A_STRIDE_B + 16);
        }
#pragma unroll
        for (int t = 0; t < 8; t++) {
            float4 bf = __ldg(tf + ((size_t)c * NT + t) * 32);
            uint32_t bh0 = __float_as_uint(bf.x), bh1 = __float_as_uint(bf.y);
            uint32_t bl0 = __float_as_uint(bf.z), bl1 = __float_as_uint(bf.w);
#pragma unroll
            for (int m = 0; m < 2; m++) {
                mma_f16(acc[m][t], ah[m], bh0, bh1);
                mma_f16(acc[m][t], al[m], bh0, bh1);
                mma_f16(acc[m][t], ah[m], bl0, bl1);
            }
        }
    }

#pragma unroll
    for (int m = 0; m < 2; m++) {
        int r0 = block_row + warp_row * 32 + m * 16 + g;
        int r1 = r0 + 8;
#pragma unroll
        for (int t = 0; t < 8; t++) {
            int col = warp_col * 64 + t * 8 + 2 * tig;
            if (r0 < N_NODES)
                *(float2*)(Y + (size_t)r0 * OUT + col) = make_float2(acc[m][t][0], acc[m][t][1]);
            if (r1 < N_NODES)
                *(float2*)(Y + (size_t)r1 * OUT + col) = make_float2(acc[m][t][2], acc[m][t][3]);
        }
    }
}

// ---------------------------------------------------------------------------
// Gather SpMM (r11 exact form): one warp per row, float4/lane, batch-4 MLP.
// Self-cleaning: each warp zeroes its row counter after reading; row-0's
// warp zeroes the overflow count and the frag flag for the next replay.
// ---------------------------------------------------------------------------
__global__ __launch_bounds__(256)
void spmm_gather_kernel(const float* __restrict__ Y, float* __restrict__ out) {
    int row  = blockIdx.x * 8 + (threadIdx.x >> 5);
    int lane = threadIdx.x & 31;
    if (row >= N_NODES) return;

    int cnt_full = g_cnt[row];
    int cnt = cnt_full > CAP ? CAP : cnt_full;

    const uint2* bkt = g_bkt + (size_t)row * CAP;
    float4 acc = make_float4(0.f, 0.f, 0.f, 0.f);

    int nb = cnt >> 2;
    for (int b = 0; b < nb; b++) {
        uint4 e01 = *(const uint4*)(bkt + 4 * b);
        uint4 e23 = *(const uint4*)(bkt + 4 * b + 2);
        float4 y0 = __ldg((const float4*)(Y + (size_t)e01.x * OUT) + lane);
        float4 y1 = __ldg((const float4*)(Y + (size_t)e01.z * OUT) + lane);
        float4 y2 = __ldg((const float4*)(Y + (size_t)e23.x * OUT) + lane);
        float4 y3 = __ldg((const float4*)(Y + (size_t)e23.z * OUT) + lane);
        float v0 = __uint_as_float(e01.y), v1 = __uint_as_float(e01.w);
        float v2 = __uint_as_float(e23.y), v3 = __uint_as_float(e23.w);
        acc.x += v0 * y0.x; acc.y += v0 * y0.y; acc.z += v0 * y0.z; acc.w += v0 * y0.w;
        acc.x += v1 * y1.x; acc.y += v1 * y1.y; acc.z += v1 * y1.z; acc.w += v1 * y1.w;
        acc.x += v2 * y2.x; acc.y += v2 * y2.y; acc.z += v2 * y2.z; acc.w += v2 * y2.w;
        acc.x += v3 * y3.x; acc.y += v3 * y3.y; acc.z += v3 * y3.z; acc.w += v3 * y3.w;
    }
    for (int i = nb * 4; i < cnt; i++) {
        uint2 e = bkt[i];
        float4 y = __ldg((const float4*)(Y + (size_t)e.x * OUT) + lane);
        float v = __uint_as_float(e.y);
        acc.x += v * y.x; acc.y += v * y.y; acc.z += v * y.z; acc.w += v * y.w;
    }

    // Overflow: only the owning warp scans (dead for this input: deg << CAP).
    if (cnt_full > CAP) {
        int n = g_cnt[N_NODES];
        for (int i = 0; i < n; i++) {
            if (g_ovf_row[i] == row) {
                uint2 e = g_ovf_cv[i];
                float4 y = __ldg((const float4*)(Y + (size_t)e.x * OUT) + lane);
                float v = __uint_as_float(e.y);
                acc.x += v * y.x; acc.y += v * y.y; acc.z += v * y.z; acc.w += v * y.w;
            }
        }
    }

    ((float4*)(out + (size_t)row * OUT))[lane] = acc;

    // Self-clean for the next graph replay.
    if (lane == 0) {
        g_cnt[row] = 0;
        if (row == 0) {
            g_cnt[N_NODES] = 0;
            g_frag_done    = 0;
        }
    }
}

// ---------------------------------------------------------------------------
extern "C" void kernel_launch(void* const* d_in, const int* in_sizes, int n_in,
                              void* d_out, int out_size) {
    const int*   row_idx = (const int*)d_in[0];
    const int*   col_idx = (const int*)d_in[1];
    const float* vals    = (const float*)d_in[2];
    const float* x       = (const float*)d_in[3];
    const float* theta   = (const float*)d_in[4];
    float*       out     = (float*)d_out;

    float* Y;
    cudaGetSymbolAddress((void**)&Y, g_Y);

    // Fused: frag blocks + bucket blocks + GEMM tile blocks (one launch).
    cudaFuncSetAttribute(gemm_fused_kernel,
                         cudaFuncAttributeMaxDynamicSharedMemorySize, GEMM_SMEM);
    gemm_fused_kernel<<<FUSED_BLOCKS, 256, GEMM_SMEM>>>(x, row_idx, col_idx,
                                                        vals, theta, Y);

    // Gather: 1 warp per row; self-cleans counters for the next replay.
    spmm_gather_kernel<<<(N_NODES + 7) / 8, 256>>>(Y, out);
}

// round 15
// speedup vs baseline: 1.2210x; 1.0660x over previous
#include <cuda_runtime.h>
#include <cuda_fp16.h>
#include <cuda_bf16.h>
#include <cstdint>

#define N_NODES 100000
#define KF      192
#define OUT     128
#define NNZ     400000

#define KCHUNKS 12                 // K=192, 16 per mma
#define NT      16                 // 128 cols / 8
#define CAP     32                 // per-row edge bucket capacity (max deg ~20)

#define FRAG_BLOCKS   24           // 24*256 = 6144 frag entries
#define BUCKET_BLOCKS 196          // 196*2048 = 401408 >= NNZ
#define EDGES_PER_BUCKET_BLOCK 2048
#define TILE_BLOCKS ((N_NODES + 127) / 128)     // 782
#define FUSED_BLOCKS (FRAG_BLOCKS + BUCKET_BLOCKS + TILE_BLOCKS)

// ---------------------------------------------------------------------------
// Global scratch. Self-cleaning across graph replays:
//  - g_cnt[row] zeroed by the gather warp owning the row
//  - g_cnt[N_NODES] (overflow count) + g_frag_done zeroed by row-0's warp
// First call relies on static zero-init of __device__ globals.
// ---------------------------------------------------------------------------
__device__ float  g_Y[(size_t)N_NODES * OUT];
__device__ float4 g_tfrag[KCHUNKS * NT * 32];       // fp16 hi/lo B-fragments
__device__ int    g_cnt[N_NODES + 1];
__device__ int    g_frag_done;                      // frag-role completion flag
__device__ __align__(16) uint2 g_bkt[(size_t)N_NODES * CAP];  // {col, val bits}
__device__ int    g_ovf_row[NNZ];                   // overflow rows
__device__ uint2  g_ovf_cv[NNZ];                    // overflow {col, val bits}

// ---------------------------------------------------------------------------
// fp16 helpers
// ---------------------------------------------------------------------------
__device__ __forceinline__ uint32_t pack_h2(float a, float b) {
    __half2 h = __floats2half2_rn(a, b);
    return *(uint32_t*)&h;
}
__device__ __forceinline__ float2 unpack_h2(uint32_t u) {
    __half2 h = *(__half2*)&u;
    return __half22float2(h);
}
__device__ __forceinline__ void mma_f16(float* c, const uint32_t* a,
                                        uint32_t b0, uint32_t b1) {
    asm volatile(
        "mma.sync.aligned.m16n8k16.row.col.f32.f16.f16.f32 "
        "{%0,%1,%2,%3}, {%4,%5,%6,%7}, {%8,%9}, {%0,%1,%2,%3};"
        : "+f"(c[0]), "+f"(c[1]), "+f"(c[2]), "+f"(c[3])
        : "r"(a[0]), "r"(a[1]), "r"(a[2]), "r"(a[3]), "r"(b0), "r"(b1));
}

// ---------------------------------------------------------------------------
// Fused launch, 3 block roles (in scheduling order):
//   [0, FRAG_BLOCKS)              : theta fp16 hi/lo B-fragments + flag
//   [FRAG_BLOCKS, +BUCKET_BLOCKS) : bucket a 2048-edge slice
//   rest                          : one 128x128 GEMM tile (spins on frag flag
//                                   after staging A)
// ---------------------------------------------------------------------------
#define A_STRIDE_B 400                    // 200 halves per row (192 + 8 pad)
#define SM_ALO     (128 * A_STRIDE_B)
#define GEMM_SMEM  (2 * 128 * A_STRIDE_B) // 102,400 B

__global__ __launch_bounds__(256, 2)
void gemm_fused_kernel(const float* __restrict__ x,
                       const int* __restrict__ row_idx,
                       const int* __restrict__ col_idx,
                       const float* __restrict__ vals,
                       const float* __restrict__ theta,
                       float* __restrict__ Y) {
    extern __shared__ char smem[];
    const int tid = threadIdx.x;

    // ---------------- frag role ----------------
    if (blockIdx.x < FRAG_BLOCKS) {
        int i = blockIdx.x * 256 + tid;   // i < 6144 always
        int lane = i & 31;
        int tt   = (i >> 5) & 15;
        int c    = i >> 9;
        int g    = lane >> 2;
        int tig  = lane & 3;
        int k    = c * 16 + 2 * tig;
        int n    = tt * 8 + g;

        float f00 = theta[(k    ) * OUT + n];
        float f01 = theta[(k + 1) * OUT + n];
        float f10 = theta[(k + 8) * OUT + n];
        float f11 = theta[(k + 9) * OUT + n];

        uint32_t bh0 = pack_h2(f00, f01);
        uint32_t bh1 = pack_h2(f10, f11);
        float2 h0 = unpack_h2(bh0), h1 = unpack_h2(bh1);
        uint32_t bl0 = pack_h2(f00 - h0.x, f01 - h0.y);
        uint32_t bl1 = pack_h2(f10 - h1.x, f11 - h1.y);

        g_tfrag[i] = make_float4(__uint_as_float(bh0), __uint_as_float(bh1),
                                 __uint_as_float(bl0), __uint_as_float(bl1));
        __threadfence();
        __syncthreads();
        if (tid == 0) atomicAdd(&g_frag_done, 1);
        return;
    }

    // ---------------- bucket role ----------------
    if (blockIdx.x < FRAG_BLOCKS + BUCKET_BLOCKS) {
        int base = (blockIdx.x - FRAG_BLOCKS) * EDGES_PER_BUCKET_BLOCK + tid;
#pragma unroll
        for (int j = 0; j < 8; j++) {
            int e = base + j * 256;
            if (e < NNZ) {
                int   r = __ldg(row_idx + e);
                int   c = __ldg(col_idx + e);
                float v = __ldg(vals + e);
                int pos = atomicAdd(&g_cnt[r], 1);
                if (pos < CAP) {
                    g_bkt[(size_t)r * CAP + pos] =
                        make_uint2((unsigned)c, __float_as_uint(v));
                } else {
                    int o = atomicAdd(&g_cnt[N_NODES], 1);
                    g_ovf_row[o] = r;
                    g_ovf_cv[o]  = make_uint2((unsigned)c, __float_as_uint(v));
                }
            }
        }
        return;
    }

    // ---------------- GEMM tile role ----------------
    char* sAh = smem;
    char* sAl = smem + SM_ALO;
    const int block_row = (blockIdx.x - FRAG_BLOCKS - BUCKET_BLOCKS) * 128;

    for (int i = tid; i < 128 * 48; i += 256) {
        int r = i / 48;
        int q = i - r * 48;
        int row = block_row + r;
        float4 v = make_float4(0.f, 0.f, 0.f, 0.f);
        if (row < N_NODES) v = ((const float4*)(x + (size_t)row * KF))[q];

        uint32_t h01 = pack_h2(v.x, v.y);
        uint32_t h23 = pack_h2(v.z, v.w);
        float2 f01 = unpack_h2(h01), f23 = unpack_h2(h23);
        uint32_t l01 = pack_h2(v.x - f01.x, v.y - f01.y);
        uint32_t l23 = pack_h2(v.z - f23.x, v.w - f23.y);

        uint32_t off = r * A_STRIDE_B + q * 8;
        *(uint2*)(sAh + off) = make_uint2(h01, h23);
        *(uint2*)(sAl + off) = make_uint2(l01, l23);
    }
    __syncthreads();

    // Wait for frag role (normally already done: frag blocks are wave-1).
    if (tid == 0) {
        while (*(volatile int*)&g_frag_done < FRAG_BLOCKS) { }
    }
    __syncthreads();

    const int lane     = tid & 31;
    const int wid      = tid >> 5;
    const int warp_row = wid & 3;
    const int warp_col = wid >> 2;
    const int g        = lane >> 2;
    const int tig      = lane & 3;

    float acc[2][8][4];
#pragma unroll
    for (int m = 0; m < 2; m++)
#pragma unroll
        for (int t = 0; t < 8; t++)
#pragma unroll
            for (int j = 0; j < 4; j++) acc[m][t][j] = 0.0f;

    const uint32_t abase = (warp_row * 32 + g) * A_STRIDE_B + 2 * tig * 2;
    const float4*  tf    = g_tfrag + (size_t)(warp_col * 8) * 32 + lane;

#pragma unroll 2
    for (int c = 0; c < KCHUNKS; c++) {
        const uint32_t koff = c * 32;
        uint32_t ah[2][4], al[2][4];
#pragma unroll
        for (int m = 0; m < 2; m++) {
            uint32_t o = abase + m * 16 * A_STRIDE_B + koff;
            ah[m][0] = *(const uint32_t*)(sAh + o);
            ah[m][1] = *(const uint32_t*)(sAh + o + 8 * A_STRIDE_B);
            ah[m][2] = *(const uint32_t*)(sAh + o + 16);
            ah[m][3] = *(const uint32_t*)(sAh + o + 8 * A_STRIDE_B + 16);
            al[m][0] = *(const uint32_t*)(sAl + o);
            al[m][1] = *(const uint32_t*)(sAl + o + 8 * A_STRIDE_B);
            al[m][2] = *(const uint32_t*)(sAl + o + 16);
            al[m][3] = *(const uint32_t*)(sAl + o + 8 * A_STRIDE_B + 16);
        }
#pragma unroll
        for (int t = 0; t < 8; t++) {
            float4 bf = __ldg(tf + ((size_t)c * NT + t) * 32);
            uint32_t bh0 = __float_as_uint(bf.x), bh1 = __float_as_uint(bf.y);
            uint32_t bl0 = __float_as_uint(bf.z), bl1 = __float_as_uint(bf.w);
#pragma unroll
            for (int m = 0; m < 2; m++) {
                mma_f16(acc[m][t], ah[m], bh0, bh1);
                mma_f16(acc[m][t], al[m], bh0, bh1);
                mma_f16(acc[m][t], ah[m], bl0, bl1);
            }
        }
    }

#pragma unroll
    for (int m = 0; m < 2; m++) {
        int r0 = block_row + warp_row * 32 + m * 16 + g;
        int r1 = r0 + 8;
#pragma unroll
        for (int t = 0; t < 8; t++) {
            int col = warp_col * 64 + t * 8 + 2 * tig;
            if (r0 < N_NODES)
                *(float2*)(Y + (size_t)r0 * OUT + col) = make_float2(acc[m][t][0], acc[m][t][1]);
            if (r1 < N_NODES)
                *(float2*)(Y + (size_t)r1 * OUT + col) = make_float2(acc[m][t][2], acc[m][t][3]);
        }
    }
}

// ---------------------------------------------------------------------------
// Gather SpMM: one warp per row, float4/lane, batch-4 MLP. Overflow fixup
// (dead for this input: deg << CAP) runs AFTER the store as red.global adds
// on top of the stored partial — same thread, same addresses, so ordered;
// keeps the hot path's register count low. Self-cleans counters for replay.
// ---------------------------------------------------------------------------
__global__ __launch_bounds__(256)
void spmm_gather_kernel(const float* __restrict__ Y, float* __restrict__ out) {
    int row  = blockIdx.x * 8 + (threadIdx.x >> 5);
    int lane = threadIdx.x & 31;
    if (row >= N_NODES) return;

    int cnt_full = g_cnt[row];
    int cnt = cnt_full > CAP ? CAP : cnt_full;

    const uint2* bkt = g_bkt + (size_t)row * CAP;
    float4 acc = make_float4(0.f, 0.f, 0.f, 0.f);

    int nb = cnt >> 2;
    for (int b = 0; b < nb; b++) {
        uint4 e01 = *(const uint4*)(bkt + 4 * b);
        uint4 e23 = *(const uint4*)(bkt + 4 * b + 2);
        float4 y0 = __ldg((const float4*)(Y + (size_t)e01.x * OUT) + lane);
        float4 y1 = __ldg((const float4*)(Y + (size_t)e01.z * OUT) + lane);
        float4 y2 = __ldg((const float4*)(Y + (size_t)e23.x * OUT) + lane);
        float4 y3 = __ldg((const float4*)(Y + (size_t)e23.z * OUT) + lane);
        float v0 = __uint_as_float(e01.y), v1 = __uint_as_float(e01.w);
        float v2 = __uint_as_float(e23.y), v3 = __uint_as_float(e23.w);
        acc.x += v0 * y0.x; acc.y += v0 * y0.y; acc.z += v0 * y0.z; acc.w += v0 * y0.w;
        acc.x += v1 * y1.x; acc.y += v1 * y1.y; acc.z += v1 * y1.z; acc.w += v1 * y1.w;
        acc.x += v2 * y2.x; acc.y += v2 * y2.y; acc.z += v2 * y2.z; acc.w += v2 * y2.w;
        acc.x += v3 * y3.x; acc.y += v3 * y3.y; acc.z += v3 * y3.z; acc.w += v3 * y3.w;
    }
    for (int i = nb * 4; i < cnt; i++) {
        uint2 e = bkt[i];
        float4 y = __ldg((const float4*)(Y + (size_t)e.x * OUT) + lane);
        float v = __uint_as_float(e.y);
        acc.x += v * y.x; acc.y += v * y.y; acc.z += v * y.z; acc.w += v * y.w;
    }

    ((float4*)(out + (size_t)row * OUT))[lane] = acc;

    // Cold overflow fixup (after the store; owner-exclusive, ordered).
    if (cnt_full > CAP) {
        int n = g_cnt[N_NODES];
        for (int i = 0; i < n; i++) {
            if (g_ovf_row[i] == row) {
                uint2 e = g_ovf_cv[i];
                float4 y = __ldg((const float4*)(Y + (size_t)e.x * OUT) + lane);
                float v = __uint_as_float(e.y);
                float* o = out + (size_t)row * OUT + lane * 4;
                asm volatile("red.global.add.v4.f32 [%0], {%1,%2,%3,%4};"
                             :: "l"(o), "f"(v * y.x), "f"(v * y.y),
                                "f"(v * y.z), "f"(v * y.w) : "memory");
            }
        }
    }

    // Self-clean for the next graph replay.
    if (lane == 0) {
        g_cnt[row] = 0;
        if (row == 0) {
            g_cnt[N_NODES] = 0;
            g_frag_done    = 0;
        }
    }
}

// ---------------------------------------------------------------------------
extern "C" void kernel_launch(void* const* d_in, const int* in_sizes, int n_in,
                              void* d_out, int out_size) {
    const int*   row_idx = (const int*)d_in[0];
    const int*   col_idx = (const int*)d_in[1];
    const float* vals    = (const float*)d_in[2];
    const float* x       = (const float*)d_in[3];
    const float* theta   = (const float*)d_in[4];
    float*       out     = (float*)d_out;

    float* Y;
    cudaGetSymbolAddress((void**)&Y, g_Y);

    // Fused: frag blocks + bucket blocks + GEMM tile blocks (one launch).
    cudaFuncSetAttribute(gemm_fused_kernel,
                         cudaFuncAttributeMaxDynamicSharedMemorySize, GEMM_SMEM);
    gemm_fused_kernel<<<FUSED_BLOCKS, 256, GEMM_SMEM>>>(x, row_idx, col_idx,
                                                        vals, theta, Y);

    // Gather: 1 warp per row; self-cleans counters for the next replay.
    spmm_gather_kernel<<<(N_NODES + 7) / 8, 256>>>(Y, out);
}

// round 16
// speedup vs baseline: 1.2784x; 1.0470x over previous
#include <cuda_runtime.h>
#include <cuda_fp16.h>
#include <cuda_bf16.h>
#include <cstdint>

#define N_NODES 100000
#define KF      192
#define OUT     128
#define NNZ     400000

#define KCHUNKS 12                 // K=192, 16 per mma
#define NT      16                 // 128 cols / 8
#define CAP     32                 // per-row edge bucket capacity (max deg ~20)

#define FRAG_BLOCKS   24           // 24*256 = 6144 frag entries
#define BUCKET_BLOCKS 196          // 196*2048 = 401408 >= NNZ
#define EDGES_PER_BUCKET_BLOCK 2048
#define TILE_BLOCKS ((N_NODES + 127) / 128)     // 782
#define FUSED_BLOCKS (FRAG_BLOCKS + BUCKET_BLOCKS + TILE_BLOCKS)

// ---------------------------------------------------------------------------
// Global scratch. Self-cleaning across graph replays:
//  - g_cnt[row] zeroed by the gather warp owning the row
//  - g_cnt[N_NODES] (overflow count) + g_frag_done zeroed by row-0's warp
// First call relies on static zero-init of __device__ globals. Bucket cols
// are always in-range (zero-init or valid old cols), so speculative Y loads
// from unread bucket slots are safe.
// ---------------------------------------------------------------------------
__device__ float  g_Y[(size_t)N_NODES * OUT];
__device__ float4 g_tfrag[KCHUNKS * NT * 32];       // fp16 hi/lo B-fragments
__device__ int    g_cnt[N_NODES + 1];
__device__ int    g_frag_done;                      // frag-role completion flag
__device__ __align__(16) uint2 g_bkt[(size_t)N_NODES * CAP];  // {col, val bits}
__device__ int    g_ovf_row[NNZ];                   // overflow rows
__device__ uint2  g_ovf_cv[NNZ];                    // overflow {col, val bits}

// ---------------------------------------------------------------------------
// fp16 helpers
// ---------------------------------------------------------------------------
__device__ __forceinline__ uint32_t pack_h2(float a, float b) {
    __half2 h = __floats2half2_rn(a, b);
    return *(uint32_t*)&h;
}
__device__ __forceinline__ float2 unpack_h2(uint32_t u) {
    __half2 h = *(__half2*)&u;
    return __half22float2(h);
}
__device__ __forceinline__ void mma_f16(float* c, const uint32_t* a,
                                        uint32_t b0, uint32_t b1) {
    asm volatile(
        "mma.sync.aligned.m16n8k16.row.col.f32.f16.f16.f32 "
        "{%0,%1,%2,%3}, {%4,%5,%6,%7}, {%8,%9}, {%0,%1,%2,%3};"
        : "+f"(c[0]), "+f"(c[1]), "+f"(c[2]), "+f"(c[3])
        : "r"(a[0]), "r"(a[1]), "r"(a[2]), "r"(a[3]), "r"(b0), "r"(b1));
}

// ---------------------------------------------------------------------------
// Fused launch, 3 block roles (in scheduling order):
//   [0, FRAG_BLOCKS)              : theta fp16 hi/lo B-fragments + flag
//   [FRAG_BLOCKS, +BUCKET_BLOCKS) : bucket a 2048-edge slice
//   rest                          : one 128x128 GEMM tile (spins on frag flag
//                                   after staging A)
// ---------------------------------------------------------------------------
#define A_STRIDE_B 400                    // 200 halves per row (192 + 8 pad)
#define SM_ALO     (128 * A_STRIDE_B)
#define GEMM_SMEM  (2 * 128 * A_STRIDE_B) // 102,400 B

__global__ __launch_bounds__(256, 2)
void gemm_fused_kernel(const float* __restrict__ x,
                       const int* __restrict__ row_idx,
                       const int* __restrict__ col_idx,
                       const float* __restrict__ vals,
                       const float* __restrict__ theta,
                       float* __restrict__ Y) {
    extern __shared__ char smem[];
    const int tid = threadIdx.x;

    // ---------------- frag role ----------------
    if (blockIdx.x < FRAG_BLOCKS) {
        int i = blockIdx.x * 256 + tid;   // i < 6144 always
        int lane = i & 31;
        int tt   = (i >> 5) & 15;
        int c    = i >> 9;
        int g    = lane >> 2;
        int tig  = lane & 3;
        int k    = c * 16 + 2 * tig;
        int n    = tt * 8 + g;

        float f00 = theta[(k    ) * OUT + n];
        float f01 = theta[(k + 1) * OUT + n];
        float f10 = theta[(k + 8) * OUT + n];
        float f11 = theta[(k + 9) * OUT + n];

        uint32_t bh0 = pack_h2(f00, f01);
        uint32_t bh1 = pack_h2(f10, f11);
        float2 h0 = unpack_h2(bh0), h1 = unpack_h2(bh1);
        uint32_t bl0 = pack_h2(f00 - h0.x, f01 - h0.y);
        uint32_t bl1 = pack_h2(f10 - h1.x, f11 - h1.y);

        g_tfrag[i] = make_float4(__uint_as_float(bh0), __uint_as_float(bh1),
                                 __uint_as_float(bl0), __uint_as_float(bl1));
        __threadfence();
        __syncthreads();
        if (tid == 0) atomicAdd(&g_frag_done, 1);
        return;
    }

    // ---------------- bucket role ----------------
    if (blockIdx.x < FRAG_BLOCKS + BUCKET_BLOCKS) {
        int base = (blockIdx.x - FRAG_BLOCKS) * EDGES_PER_BUCKET_BLOCK + tid;
#pragma unroll
        for (int j = 0; j < 8; j++) {
            int e = base + j * 256;
            if (e < NNZ) {
                int   r = __ldg(row_idx + e);
                int   c = __ldg(col_idx + e);
                float v = __ldg(vals + e);
                int pos = atomicAdd(&g_cnt[r], 1);
                if (pos < CAP) {
                    g_bkt[(size_t)r * CAP + pos] =
                        make_uint2((unsigned)c, __float_as_uint(v));
                } else {
                    int o = atomicAdd(&g_cnt[N_NODES], 1);
                    g_ovf_row[o] = r;
                    g_ovf_cv[o]  = make_uint2((unsigned)c, __float_as_uint(v));
                }
            }
        }
        return;
    }

    // ---------------- GEMM tile role ----------------
    char* sAh = smem;
    char* sAl = smem + SM_ALO;
    const int block_row = (blockIdx.x - FRAG_BLOCKS - BUCKET_BLOCKS) * 128;

    for (int i = tid; i < 128 * 48; i += 256) {
        int r = i / 48;
        int q = i - r * 48;
        int row = block_row + r;
        float4 v = make_float4(0.f, 0.f, 0.f, 0.f);
        if (row < N_NODES) v = ((const float4*)(x + (size_t)row * KF))[q];

        uint32_t h01 = pack_h2(v.x, v.y);
        uint32_t h23 = pack_h2(v.z, v.w);
        float2 f01 = unpack_h2(h01), f23 = unpack_h2(h23);
        uint32_t l01 = pack_h2(v.x - f01.x, v.y - f01.y);
        uint32_t l23 = pack_h2(v.z - f23.x, v.w - f23.y);

        uint32_t off = r * A_STRIDE_B + q * 8;
        *(uint2*)(sAh + off) = make_uint2(h01, h23);
        *(uint2*)(sAl + off) = make_uint2(l01, l23);
    }
    __syncthreads();

    // Wait for frag role (normally already done: frag blocks are wave-1).
    if (tid == 0) {
        while (*(volatile int*)&g_frag_done < FRAG_BLOCKS) { }
    }
    __syncthreads();

    const int lane     = tid & 31;
    const int wid      = tid >> 5;
    const int warp_row = wid & 3;
    const int warp_col = wid >> 2;
    const int g        = lane >> 2;
    const int tig      = lane & 3;

    float acc[2][8][4];
#pragma unroll
    for (int m = 0; m < 2; m++)
#pragma unroll
        for (int t = 0; t < 8; t++)
#pragma unroll
            for (int j = 0; j < 4; j++) acc[m][t][j] = 0.0f;

    const uint32_t abase = (warp_row * 32 + g) * A_STRIDE_B + 2 * tig * 2;
    const float4*  tf    = g_tfrag + (size_t)(warp_col * 8) * 32 + lane;

#pragma unroll 2
    for (int c = 0; c < KCHUNKS; c++) {
        const uint32_t koff = c * 32;
        uint32_t ah[2][4], al[2][4];
#pragma unroll
        for (int m = 0; m < 2; m++) {
            uint32_t o = abase + m * 16 * A_STRIDE_B + koff;
            ah[m][0] = *(const uint32_t*)(sAh + o);
            ah[m][1] = *(const uint32_t*)(sAh + o + 8 * A_STRIDE_B);
            ah[m][2] = *(const uint32_t*)(sAh + o + 16);
            ah[m][3] = *(const uint32_t*)(sAh + o + 8 * A_STRIDE_B + 16);
            al[m][0] = *(const uint32_t*)(sAl + o);
            al[m][1] = *(const uint32_t*)(sAl + o + 8 * A_STRIDE_B);
            al[m][2] = *(const uint32_t*)(sAl + o + 16);
            al[m][3] = *(const uint32_t*)(sAl + o + 8 * A_STRIDE_B + 16);
        }
#pragma unroll
        for (int t = 0; t < 8; t++) {
            float4 bf = __ldg(tf + ((size_t)c * NT + t) * 32);
            uint32_t bh0 = __float_as_uint(bf.x), bh1 = __float_as_uint(bf.y);
            uint32_t bl0 = __float_as_uint(bf.z), bl1 = __float_as_uint(bf.w);
#pragma unroll
            for (int m = 0; m < 2; m++) {
                mma_f16(acc[m][t], ah[m], bh0, bh1);
                mma_f16(acc[m][t], al[m], bh0, bh1);
                mma_f16(acc[m][t], ah[m], bl0, bl1);
            }
        }
    }

#pragma unroll
    for (int m = 0; m < 2; m++) {
        int r0 = block_row + warp_row * 32 + m * 16 + g;
        int r1 = r0 + 8;
#pragma unroll
        for (int t = 0; t < 8; t++) {
            int col = warp_col * 64 + t * 8 + 2 * tig;
            if (r0 < N_NODES)
                *(float2*)(Y + (size_t)r0 * OUT + col) = make_float2(acc[m][t][0], acc[m][t][1]);
            if (r1 < N_NODES)
                *(float2*)(Y + (size_t)r1 * OUT + col) = make_float2(acc[m][t][2], acc[m][t][3]);
        }
    }
}

// ---------------------------------------------------------------------------
// Gather SpMM: one warp per row, float4/lane, batch-4 MLP.
// Dependency-chain fix: g_cnt[row] and the first bucket batch (entries 0-3)
// are issued CONCURRENTLY (independent addresses); the first batch's vals
// are masked by cnt. Speculative Y loads from unread slots are safe (cols
// always in-range). Batches >= 1 use the same masked form. Overflow fixup
// (dead for this input) runs after the store; self-cleans counters.
// ---------------------------------------------------------------------------
__global__ __launch_bounds__(256)
void spmm_gather_kernel(const float* __restrict__ Y, float* __restrict__ out) {
    int row  = blockIdx.x * 8 + (threadIdx.x >> 5);
    int lane = threadIdx.x & 31;
    if (row >= N_NODES) return;

    const uint2* bkt = g_bkt + (size_t)row * CAP;

    // Issue cnt + batch-0 metadata together (no dependency between them).
    int  cnt_full = g_cnt[row];
    uint4 e01 = *(const uint4*)(bkt);       // entries 0,1
    uint4 e23 = *(const uint4*)(bkt + 2);   // entries 2,3

    int cnt = cnt_full > CAP ? CAP : cnt_full;
    float4 acc = make_float4(0.f, 0.f, 0.f, 0.f);

    // Batch 0: unconditional Y loads, cnt-masked vals.
    {
        float v0 = (cnt > 0) ? __uint_as_float(e01.y) : 0.f;
        float v1 = (cnt > 1) ? __uint_as_float(e01.w) : 0.f;
        float v2 = (cnt > 2) ? __uint_as_float(e23.y) : 0.f;
        float v3 = (cnt > 3) ? __uint_as_float(e23.w) : 0.f;
        float4 y0 = __ldg((const float4*)(Y + (size_t)e01.x * OUT) + lane);
        float4 y1 = __ldg((const float4*)(Y + (size_t)e01.z * OUT) + lane);
        float4 y2 = __ldg((const float4*)(Y + (size_t)e23.x * OUT) + lane);
        float4 y3 = __ldg((const float4*)(Y + (size_t)e23.z * OUT) + lane);
        acc.x += v0 * y0.x; acc.y += v0 * y0.y; acc.z += v0 * y0.z; acc.w += v0 * y0.w;
        acc.x += v1 * y1.x; acc.y += v1 * y1.y; acc.z += v1 * y1.z; acc.w += v1 * y1.w;
        acc.x += v2 * y2.x; acc.y += v2 * y2.y; acc.z += v2 * y2.z; acc.w += v2 * y2.w;
        acc.x += v3 * y3.x; acc.y += v3 * y3.y; acc.z += v3 * y3.z; acc.w += v3 * y3.w;
    }

    // Batches 1..nb-1 (37% of rows), masked the same way.
    int nb = (cnt + 3) >> 2;
    for (int b = 1; b < nb; b++) {
        int base = 4 * b;
        uint4 f01 = *(const uint4*)(bkt + base);
        uint4 f23 = *(const uint4*)(bkt + base + 2);
        float v0 = (base + 0 < cnt) ? __uint_as_float(f01.y) : 0.f;
        float v1 = (base + 1 < cnt) ? __uint_as_float(f01.w) : 0.f;
        float v2 = (base + 2 < cnt) ? __uint_as_float(f23.y) : 0.f;
        float v3 = (base + 3 < cnt) ? __uint_as_float(f23.w) : 0.f;
        float4 y0 = __ldg((const float4*)(Y + (size_t)f01.x * OUT) + lane);
        float4 y1 = __ldg((const float4*)(Y + (size_t)f01.z * OUT) + lane);
        float4 y2 = __ldg((const float4*)(Y + (size_t)f23.x * OUT) + lane);
        float4 y3 = __ldg((const float4*)(Y + (size_t)f23.z * OUT) + lane);
        acc.x += v0 * y0.x; acc.y += v0 * y0.y; acc.z += v0 * y0.z; acc.w += v0 * y0.w;
        acc.x += v1 * y1.x; acc.y += v1 * y1.y; acc.z += v1 * y1.z; acc.w += v1 * y1.w;
        acc.x += v2 * y2.x; acc.y += v2 * y2.y; acc.z += v2 * y2.z; acc.w += v2 * y2.w;
        acc.x += v3 * y3.x; acc.y += v3 * y3.y; acc.z += v3 * y3.z; acc.w += v3 * y3.w;
    }

    ((float4*)(out + (size_t)row * OUT))[lane] = acc;

    // Cold overflow fixup (after the store; owner-exclusive, ordered).
    if (cnt_full > CAP) {
        int n = g_cnt[N_NODES];
        for (int i = 0; i < n; i++) {
            if (g_ovf_row[i] == row) {
                uint2 e = g_ovf_cv[i];
                float4 y = __ldg((const float4*)(Y + (size_t)e.x * OUT) + lane);
                float v = __uint_as_float(e.y);
                float* o = out + (size_t)row * OUT + lane * 4;
                asm volatile("red.global.add.v4.f32 [%0], {%1,%2,%3,%4};"
                             :: "l"(o), "f"(v * y.x), "f"(v * y.y),
                                "f"(v * y.z), "f"(v * y.w) : "memory");
            }
        }
    }

    // Self-clean for the next graph replay.
    if (lane == 0) {
        g_cnt[row] = 0;
        if (row == 0) {
            g_cnt[N_NODES] = 0;
            g_frag_done    = 0;
        }
    }
}

// ---------------------------------------------------------------------------
extern "C" void kernel_launch(void* const* d_in, const int* in_sizes, int n_in,
                              void* d_out, int out_size) {
    const int*   row_idx = (const int*)d_in[0];
    const int*   col_idx = (const int*)d_in[1];
    const float* vals    = (const float*)d_in[2];
    const float* x       = (const float*)d_in[3];
    const float* theta   = (const float*)d_in[4];
    float*       out     = (float*)d_out;

    float* Y;
    cudaGetSymbolAddress((void**)&Y, g_Y);

    // Fused: frag blocks + bucket blocks + GEMM tile blocks (one launch).
    cudaFuncSetAttribute(gemm_fused_kernel,
                         cudaFuncAttributeMaxDynamicSharedMemorySize, GEMM_SMEM);
    gemm_fused_kernel<<<FUSED_BLOCKS, 256, GEMM_SMEM>>>(x, row_idx, col_idx,
                                                        vals, theta, Y);

    // Gather: 1 warp per row; self-cleans counters for the next replay.
    spmm_gather_kernel<<<(N_NODES + 7) / 8, 256>>>(Y, out);
}